// round 3
// baseline (speedup 1.0000x reference)
#include <cuda_runtime.h>

// Laplacian of sphere SDF over padded one-ring graph.
// inputs (metadata order):
//   d_in[0] verts_one_ring      [N,16,3] f32  (12 float4 per node)
//   d_in[1] verts_central_nodes [N,3]    f32
//   d_in[2] one_ring_mask       [N,16,1] f32  (4 float4 per node)
// output: concat(center_sdfs [N], lap [N]) -> 2N f32
//
// One lane per quarter-node. Ring/mask via LDG.128, center loads
// cooperative+coalesced, outputs shuffle-compacted to coalesced stores.

__device__ __forceinline__ float sdf3(float x, float y, float z)
{
    float dx = x - 0.5f, dy = y - 0.5f, dz = z - 0.5f;
    return sqrtf(fmaf(dx, dx, fmaf(dy, dy, dz * dz))) - 0.25f;
}

__global__ void laplacian_sdf_kernel(const float4* __restrict__ ring4,
                                     const float* __restrict__ center,
                                     const float4* __restrict__ mask4,
                                     float* __restrict__ out,
                                     int N)
{
    long long gid = (long long)blockIdx.x * blockDim.x + threadIdx.x;
    long long node = gid >> 2;          // 4 lanes per node
    int l = (int)(gid & 3);             // quarter index: slots 4l..4l+3
    int lane = threadIdx.x & 31;

    // Cooperative, fully-coalesced center load: lanes 0..2 of each group
    // read center[node*3 + l]; the group covers 12 contiguous bytes and
    // consecutive groups are contiguous -> perfect coalescing.
    float cc = 0.0f;
    if (node < N && l < 3) cc = center[node * 3 + l];
    float cx = cc;                                        // valid on l==0
    float cy = __shfl_sync(0xffffffffu, cc, lane | 1, 32); // from l==1
    float cz = __shfl_sync(0xffffffffu, cc, lane | 2, 32); // from l==2 (|2 on l<2)
    // note: for l==0, lane|1 = group lane 1, lane|2 = group lane 2. Good.

    float sm = 0.0f, m = 0.0f, cs = 0.0f;
    if (node < N) {
        const float4* r = ring4 + node * 12 + l * 3;
        float4 a = r[0];
        float4 b = r[1];
        float4 c = r[2];
        float4 mk = mask4[node * 4 + l];

        float s0 = sdf3(a.x, a.y, a.z);
        float s1 = sdf3(a.w, b.x, b.y);
        float s2 = sdf3(b.z, b.w, c.x);
        float s3 = sdf3(c.y, c.z, c.w);

        sm = fmaf(s0, mk.x, fmaf(s1, mk.y, fmaf(s2, mk.z, s3 * mk.w)));
        m  = (mk.x + mk.y) + (mk.z + mk.w);
    }

    // 2-level segmented reduction over the 4-lane group
    sm += __shfl_xor_sync(0xffffffffu, sm, 1);
    m  += __shfl_xor_sync(0xffffffffu, m,  1);
    sm += __shfl_xor_sync(0xffffffffu, sm, 2);
    m  += __shfl_xor_sync(0xffffffffu, m,  2);

    cs = sdf3(cx, cy, cz);                 // meaningful on l==0 lanes
    float lap = fmaf(-m, cs, sm);

    // Compact the 8 group results (group-lane 0 holds them) to lanes 0..7
    // for two fully coalesced 32B stores per warp.
    float cs_c  = __shfl_sync(0xffffffffu, cs,  (lane & 7) * 4, 32);
    float lap_c = __shfl_sync(0xffffffffu, lap, (lane & 7) * 4, 32);

    // first node handled by this warp:
    long long warpNode0 = ((long long)blockIdx.x * blockDim.x
                           + (threadIdx.x & ~31)) >> 2;
    if (lane < 8) {
        long long n = warpNode0 + lane;
        if (n < N) {
            out[n]     = cs_c;
            out[N + n] = lap_c;
        }
    }
}

extern "C" void kernel_launch(void* const* d_in, const int* in_sizes, int n_in,
                              void* d_out, int out_size)
{
    const float4* ring4  = (const float4*)d_in[0];
    const float*  center = (const float*)d_in[1];
    const float4* mask4  = (const float4*)d_in[2];
    float* out = (float*)d_out;

    int N = in_sizes[1] / 3;  // verts_central_nodes has N*3 elements

    long long total = (long long)N * 4;
    int threads = 256;
    long long blocks = (total + threads - 1) / threads;

    laplacian_sdf_kernel<<<(unsigned)blocks, threads>>>(ring4, center, mask4, out, N);
}

// round 4
// speedup vs baseline: 1.1188x; 1.1188x over previous
#include <cuda_runtime.h>

// Laplacian of sphere SDF over padded one-ring graph.
// inputs (metadata order):
//   d_in[0] verts_one_ring      [N,16,3] f32  (12 float4 per node)
//   d_in[1] verts_central_nodes [N,3]    f32
//   d_in[2] one_ring_mask       [N,16,1] f32  (4 float4 per node)
// output: concat(center_sdfs [N], lap [N]) -> 2N f32
//
// One lane per HALF node (8 slots): 8 independent LDG.128 up front for max
// MLP, single shuffle-level reduction, read-once streams use .cs hint.

__device__ __forceinline__ float sdf3(float x, float y, float z)
{
    float dx = x - 0.5f, dy = y - 0.5f, dz = z - 0.5f;
    return sqrtf(fmaf(dx, dx, fmaf(dy, dy, dz * dz))) - 0.25f;
}

__global__ void laplacian_sdf_kernel(const float4* __restrict__ ring4,
                                     const float* __restrict__ center,
                                     const float4* __restrict__ mask4,
                                     float* __restrict__ out,
                                     int N)
{
    long long gid = (long long)blockIdx.x * blockDim.x + threadIdx.x;
    long long node = gid >> 1;          // 2 lanes per node
    int l = (int)(gid & 1);             // half index: slots 8l..8l+7
    if (node >= N) return;

    // 6 ring float4 + 2 mask float4, all independent -> 8 loads in flight
    const float4* r = ring4 + node * 12 + l * 6;
    float4 v0 = __ldcs(r + 0);
    float4 v1 = __ldcs(r + 1);
    float4 v2 = __ldcs(r + 2);
    float4 v3 = __ldcs(r + 3);
    float4 v4 = __ldcs(r + 4);
    float4 v5 = __ldcs(r + 5);
    const float4* mp = mask4 + node * 4 + l * 2;
    float4 mk0 = __ldcs(mp + 0);
    float4 mk1 = __ldcs(mp + 1);

    // 24 floats = 8 triples
    float s0 = sdf3(v0.x, v0.y, v0.z);
    float s1 = sdf3(v0.w, v1.x, v1.y);
    float s2 = sdf3(v1.z, v1.w, v2.x);
    float s3 = sdf3(v2.y, v2.z, v2.w);
    float s4 = sdf3(v3.x, v3.y, v3.z);
    float s5 = sdf3(v3.w, v4.x, v4.y);
    float s6 = sdf3(v4.z, v4.w, v5.x);
    float s7 = sdf3(v5.y, v5.z, v5.w);

    float smA = fmaf(s0, mk0.x, fmaf(s1, mk0.y, fmaf(s2, mk0.z, s3 * mk0.w)));
    float smB = fmaf(s4, mk1.x, fmaf(s5, mk1.y, fmaf(s6, mk1.z, s7 * mk1.w)));
    float sm = smA + smB;
    float m  = ((mk0.x + mk0.y) + (mk0.z + mk0.w))
             + ((mk1.x + mk1.y) + (mk1.z + mk1.w));

    // single-level segmented reduction over the 2-lane group
    sm += __shfl_xor_sync(0xffffffffu, sm, 1);
    m  += __shfl_xor_sync(0xffffffffu, m,  1);

    if (l == 0) {
        const float* cp = center + node * 3;
        float cs = sdf3(cp[0], cp[1], cp[2]);
        out[node]     = cs;
        out[N + node] = fmaf(-m, cs, sm);
    }
}

extern "C" void kernel_launch(void* const* d_in, const int* in_sizes, int n_in,
                              void* d_out, int out_size)
{
    const float4* ring4  = (const float4*)d_in[0];
    const float*  center = (const float*)d_in[1];
    const float4* mask4  = (const float4*)d_in[2];
    float* out = (float*)d_out;

    int N = in_sizes[1] / 3;  // verts_central_nodes has N*3 elements

    long long total = (long long)N * 2;
    int threads = 256;
    long long blocks = (total + threads - 1) / threads;

    laplacian_sdf_kernel<<<(unsigned)blocks, threads>>>(ring4, center, mask4, out, N);
}